// round 15
// baseline (speedup 1.0000x reference)
#include <cuda_runtime.h>
#include <math.h>

#define BB 2
#define NN 512
#define DIN 512
#define DM 256
#define C2LOG2E 2.885390081777927f   // 2*log2(e)

typedef unsigned long long ull;

// scratch (static device globals — no allocation)
__device__ float g_h[BB * NN * DM];    // h[b][n][d] = tanh(x@Wx+bx)
__device__ float g_p[BB * NN * DM];    // P row-major: exp2(c*(u+bp))
__device__ float g_qt[BB * DM * NN];   // Q transposed: exp2(-c*u)[b][d][n]

__device__ __forceinline__ float ex2_fast(float x) {
    float y; asm("ex2.approx.f32 %0, %1;" : "=f"(y) : "f"(x)); return y;
}
__device__ __forceinline__ float rcp_fast(float x) {
    float y; asm("rcp.approx.f32 %0, %1;" : "=f"(y) : "f"(x)); return y;
}
// ---- packed f32x2 helpers (Blackwell FFMA2 path) ----
__device__ __forceinline__ ull pack2(float lo, float hi) {
    ull r; asm("mov.b64 %0, {%1, %2};" : "=l"(r) : "f"(lo), "f"(hi)); return r;
}
__device__ __forceinline__ void unpack2(ull v, float& lo, float& hi) {
    asm("mov.b64 {%0, %1}, %2;" : "=f"(lo), "=f"(hi) : "l"(v));
}
__device__ __forceinline__ ull fma2(ull a, ull b, ull c) {
    ull d; asm("fma.rn.f32x2 %0, %1, %2, %3;" : "=l"(d) : "l"(a), "l"(b), "l"(c)); return d;
}
__device__ __forceinline__ ull mul2(ull a, ull b) {
    ull d; asm("mul.rn.f32x2 %0, %1, %2;" : "=l"(d) : "l"(a), "l"(b)); return d;
}
__device__ __forceinline__ ull add2(ull a, ull b) {
    ull d; asm("add.rn.f32x2 %0, %1, %2;" : "=l"(d) : "l"(a), "l"(b)); return d;
}

// ---------------------------------------------------------------------------
// Kernel A (f32x2): h = tanh(x @ Wx + bx), P/Q projections.
// 4 rows/block, thread owns col-pair cp (packed), K split 8-way.
// grid 256 x 1024 threads. Inner: 4 fma2 per k for 8 MACs.
// ---------------------------------------------------------------------------
__global__ __launch_bounds__(1024) void kA(const float* __restrict__ x,
                                           const float* __restrict__ pos,
                                           const float* __restrict__ Wx,
                                           const float* __restrict__ bx,
                                           const float* __restrict__ Wp,
                                           const float* __restrict__ bp) {
    __shared__ ull s_x2[DIN][4];            // x broadcast pairs, 16KB
    __shared__ ull s_part[8][4][DM / 2];    // packed partials, 32KB
    const int t = threadIdx.x;
    const int row0 = blockIdx.x * 4;
    const int cp = t & 127;
    const int c2 = cp * 2;
    const int kq = t >> 7;
    const int b = row0 / NN;
    const int n0 = row0 % NN;

    if (t < DM) {
        const float w0 = Wp[0 * DM + t], w1 = Wp[1 * DM + t];
        const float w2 = Wp[2 * DM + t], w3 = Wp[3 * DM + t];
        const float bpv = bp[t];
#pragma unroll
        for (int r = 0; r < 4; r++) {
            const float* p = pos + (row0 + r) * 4;
            float u = p[0] * w0 + p[1] * w1 + p[2] * w2 + p[3] * w3;
            g_p[(row0 + r) * DM + t] = ex2_fast(C2LOG2E * (u + bpv));
            g_qt[(b * DM + t) * NN + n0 + r] = ex2_fast(-C2LOG2E * u);
        }
    }

    for (int e = t; e < DIN * 4; e += 1024) {
        int r = e >> 9, cc = e & (DIN - 1);
        float v = x[(row0 + r) * DIN + cc];
        s_x2[cc][r] = pack2(v, v);
    }
    __syncthreads();

    ull acc0 = 0, acc1 = 0, acc2 = 0, acc3 = 0;
    const int kb = kq << 6;
#pragma unroll 8
    for (int k = 0; k < 64; k++) {
        ull wv = *(const ull*)&Wx[(kb + k) * DM + c2];          // LDG.64 coalesced
        ulonglong2 xA = *(const ulonglong2*)&s_x2[kb + k][0];   // rows 0,1 (LDS.128)
        ulonglong2 xB = *(const ulonglong2*)&s_x2[kb + k][2];   // rows 2,3
        acc0 = fma2(xA.x, wv, acc0);
        acc1 = fma2(xA.y, wv, acc1);
        acc2 = fma2(xB.x, wv, acc2);
        acc3 = fma2(xB.y, wv, acc3);
    }
    s_part[kq][0][cp] = acc0;
    s_part[kq][1][cp] = acc1;
    s_part[kq][2][cp] = acc2;
    s_part[kq][3][cp] = acc3;
    __syncthreads();

    if (t < 512) {
        const int r = t >> 7;
        const int p = t & 127;
        ull s = s_part[0][r][p];
#pragma unroll
        for (int g = 1; g < 8; g++) s = add2(s, s_part[g][r][p]);
        float lo, hi;
        unpack2(s, lo, hi);
        g_h[(row0 + r) * DM + 2 * p]     = tanhf(lo + bx[2 * p]);
        g_h[(row0 + r) * DM + 2 * p + 1] = tanhf(hi + bx[2 * p + 1]);
    }
}

// ---------------------------------------------------------------------------
// Kernel Score (R14 best, unchanged): f32x2 packed, 4 rows x 128 j per block,
// d split 8-way. grid = 1024 blocks, 512 threads.
// ---------------------------------------------------------------------------
__global__ __launch_bounds__(512) void kScore(const float* __restrict__ w,
                                              float* __restrict__ attn_out) {
    __shared__ ull s_pib[DM][4];        // P broadcast pairs, 8KB
    __shared__ ull s_wn2[DM];           // (-2w,-2w), 2KB
    __shared__ ull s_part[7][4][64];    // dq=1..7 partials, 14KB
    __shared__ float s_W;

    const int t   = threadIdx.x;
    const int tj2 = t & 63;
    const int dq  = t >> 6;
    const int jt  = blockIdx.x & 3;
    const int it  = blockIdx.x >> 2;
    const int b   = it / (NN / 4);
    const int i0  = (it % (NN / 4)) * 4;
    const int j0  = jt * 128 + tj2 * 2;

    if (t < DM) {
        float wv = -2.0f * w[t];
        s_wn2[t] = pack2(wv, wv);
    }
    if (t < 32) {
        float s = 0.f;
#pragma unroll
        for (int k = 0; k < 8; k++) s += w[t + 32 * k];
#pragma unroll
        for (int o = 16; o; o >>= 1) s += __shfl_xor_sync(0xffffffffu, s, o);
        if (t == 0) s_W = s;
    }
    {
        const float* prow = g_p + (b * NN + i0) * DM;
        for (int e = t; e < 4 * DM; e += 512) {
            int r = e >> 8, d = e & (DM - 1);
            float v = prow[r * DM + d];
            s_pib[d][r] = pack2(v, v);
        }
    }
    __syncthreads();

    const ull ONE2 = pack2(1.0f, 1.0f);
    ull acc0 = 0, acc1 = 0, acc2 = 0, acc3 = 0;
    const float* qp = g_qt + b * DM * NN + j0;
    const int db = dq << 5;
    ull qbuf[4];
#pragma unroll
    for (int p = 0; p < 4; p++) qbuf[p] = *(const ull*)(qp + (db + p) * NN);

    for (int d0 = db; d0 < db + 32; d0 += 4) {
        ull qc[4];
#pragma unroll
        for (int p = 0; p < 4; p++) qc[p] = qbuf[p];
        if (d0 + 4 < db + 32) {
#pragma unroll
            for (int p = 0; p < 4; p++) qbuf[p] = *(const ull*)(qp + (d0 + 4 + p) * NN);
        }
#pragma unroll
        for (int dd = 0; dd < 4; dd++) {
            const int d = d0 + dd;
            const ull wn2 = s_wn2[d];
            ulonglong2 piA = *(const ulonglong2*)&s_pib[d][0];
            ulonglong2 piB = *(const ulonglong2*)&s_pib[d][2];
            const ull qj2 = qc[dd];
            ull de0 = fma2(piA.x, qj2, ONE2);
            ull de1 = fma2(piA.y, qj2, ONE2);
            ull de2 = fma2(piB.x, qj2, ONE2);
            ull de3 = fma2(piB.y, qj2, ONE2);
            ull p01 = mul2(de0, de1);
            ull p23 = mul2(de2, de3);
            ull tot = mul2(p01, p23);
            float tl, th;
            unpack2(tot, tl, th);
            ull r2 = pack2(rcp_fast(tl), rcp_fast(th));
            ull i01 = mul2(r2, p23);
            ull i23 = mul2(r2, p01);
            ull w01 = mul2(wn2, i01);
            ull w23 = mul2(wn2, i23);
            acc0 = fma2(w01, de1, acc0);
            acc1 = fma2(w01, de0, acc1);
            acc2 = fma2(w23, de3, acc2);
            acc3 = fma2(w23, de2, acc3);
        }
    }
    if (dq) {
        s_part[dq - 1][0][tj2] = acc0;
        s_part[dq - 1][1][tj2] = acc1;
        s_part[dq - 1][2][tj2] = acc2;
        s_part[dq - 1][3][tj2] = acc3;
    }
    __syncthreads();
    if (dq == 0) {
        const ull W2 = pack2(s_W, s_W);
#pragma unroll
        for (int g = 0; g < 7; g++) {
            acc0 = add2(acc0, s_part[g][0][tj2]);
            acc1 = add2(acc1, s_part[g][1][tj2]);
            acc2 = add2(acc2, s_part[g][2][tj2]);
            acc3 = add2(acc3, s_part[g][3][tj2]);
        }
        float* arow = attn_out + (b * NN + i0) * NN + j0;
        *(ull*)&arow[0 * NN] = add2(acc0, W2);
        *(ull*)&arow[1 * NN] = add2(acc1, W2);
        *(ull*)&arow[2 * NN] = add2(acc2, W2);
        *(ull*)&arow[3 * NN] = add2(acc3, W2);
    }
}

// ---------------------------------------------------------------------------
// Kernel SO (f32x2 GEMM): masked softmax + output GEMM.
// Thread owns d-col pair (packed h float2) x j-group of 64; 8-way j split.
// grid = 256 blocks, 1024 threads.
// ---------------------------------------------------------------------------
__global__ __launch_bounds__(1024) void kSO(const int* __restrict__ mask,
                                            float* __restrict__ out,
                                            float* __restrict__ attn_out) {
    __shared__ float s_attn[4][NN];          // 8KB (softmax working set)
    __shared__ ull s_attn2[4][NN];           // prob broadcast pairs, 16KB
    __shared__ ull s_part[8][4][DM / 2];     // packed partials, 32KB

    const int t = threadIdx.x;
    const int blk = blockIdx.x;
    const int b = blk / (NN / 4);
    const int i0 = (blk % (NN / 4)) * 4;

    {
        const float4* src = (const float4*)(attn_out + (b * NN + i0) * NN);
        float4* dst = (float4*)&s_attn[0][0];
        for (int e = t; e < 4 * NN / 4; e += 1024) dst[e] = src[e];
    }
    __syncthreads();

    const int wid = t >> 5, lane = t & 31;
    if (wid < 4) {
        const int i = i0 + wid;
        const int4* m4 = (const int4*)(mask + (b * NN + i) * NN);
        float4* s4 = (float4*)&s_attn[wid][0];
        int4 mv[4];
        float4 sv[4];
#pragma unroll
        for (int k = 0; k < 4; k++) {
            mv[k] = m4[lane + 32 * k];
            sv[k] = s4[lane + 32 * k];
        }
        float mx = -INFINITY;
#pragma unroll
        for (int k = 0; k < 4; k++) {
            if (mv[k].x) mx = fmaxf(mx, sv[k].x);
            if (mv[k].y) mx = fmaxf(mx, sv[k].y);
            if (mv[k].z) mx = fmaxf(mx, sv[k].z);
            if (mv[k].w) mx = fmaxf(mx, sv[k].w);
        }
#pragma unroll
        for (int o = 16; o; o >>= 1) mx = fmaxf(mx, __shfl_xor_sync(0xffffffffu, mx, o));
        float sum = 0.f;
#pragma unroll
        for (int k = 0; k < 4; k++) {
            sv[k].x = mv[k].x ? __expf(sv[k].x - mx) : 0.f;
            sv[k].y = mv[k].y ? __expf(sv[k].y - mx) : 0.f;
            sv[k].z = mv[k].z ? __expf(sv[k].z - mx) : 0.f;
            sv[k].w = mv[k].w ? __expf(sv[k].w - mx) : 0.f;
            sum += sv[k].x + sv[k].y + sv[k].z + sv[k].w;
        }
#pragma unroll
        for (int o = 16; o; o >>= 1) sum += __shfl_xor_sync(0xffffffffu, sum, o);
        const float inv = (sum > 0.f) ? 1.f / sum : 0.f;
        float4* arow4 = (float4*)(attn_out + (b * NN + i) * NN);
#pragma unroll
        for (int k = 0; k < 4; k++) {
            sv[k].x *= inv; sv[k].y *= inv; sv[k].z *= inv; sv[k].w *= inv;
            arow4[lane + 32 * k] = sv[k];
            const int jb = 4 * (lane + 32 * k);
            s_attn2[wid][jb + 0] = pack2(sv[k].x, sv[k].x);
            s_attn2[wid][jb + 1] = pack2(sv[k].y, sv[k].y);
            s_attn2[wid][jb + 2] = pack2(sv[k].z, sv[k].z);
            s_attn2[wid][jb + 3] = pack2(sv[k].w, sv[k].w);
        }
    }
    __syncthreads();

    // output GEMM (f32x2): thread -> col pair cp, j-group jg (64 j's)
    {
        const int cp = t & 127;
        const int c2 = cp * 2;
        const int jg = t >> 7;
        ull o0 = 0, o1 = 0, o2 = 0, o3 = 0;
        const float* hb = g_h + b * NN * DM + c2;
        const int jb = jg * 64;
#pragma unroll 2
        for (int j = jb; j < jb + 64; j += 2) {
            ull h0 = *(const ull*)&hb[(j + 0) * DM];       // LDG.64: (h[c2],h[c2+1])
            ull h1 = *(const ull*)&hb[(j + 1) * DM];
            ulonglong2 a0 = *(const ulonglong2*)&s_attn2[0][j];  // LDS.128: 2 j's
            ulonglong2 a1 = *(const ulonglong2*)&s_attn2[1][j];
            ulonglong2 a2 = *(const ulonglong2*)&s_attn2[2][j];
            ulonglong2 a3 = *(const ulonglong2*)&s_attn2[3][j];
            o0 = fma2(a0.x, h0, o0); o0 = fma2(a0.y, h1, o0);
            o1 = fma2(a1.x, h0, o1); o1 = fma2(a1.y, h1, o1);
            o2 = fma2(a2.x, h0, o2); o2 = fma2(a2.y, h1, o2);
            o3 = fma2(a3.x, h0, o3); o3 = fma2(a3.y, h1, o3);
        }
        s_part[jg][0][cp] = o0;
        s_part[jg][1][cp] = o1;
        s_part[jg][2][cp] = o2;
        s_part[jg][3][cp] = o3;
    }
    __syncthreads();

    if (t < 512) {
        const int r = t >> 7;
        const int p = t & 127;
        ull s = s_part[0][r][p];
#pragma unroll
        for (int g = 1; g < 8; g++) s = add2(s, s_part[g][r][p]);
        *(ull*)&out[(b * NN + i0 + r) * DM + 2 * p] = s;
    }
}

// ---------------------------------------------------------------------------
extern "C" void kernel_launch(void* const* d_in, const int* in_sizes, int n_in,
                              void* d_out, int out_size) {
    const float* x    = (const float*)d_in[0];  // [2,512,512]
    const float* pos  = (const float*)d_in[1];  // [2,512,4]
    const int*   mask = (const int*)  d_in[2];  // [2,512,512]
    const float* Wx   = (const float*)d_in[3];  // [512,256]
    const float* bx   = (const float*)d_in[4];  // [256]
    const float* Wp   = (const float*)d_in[5];  // [4,256]
    const float* bp   = (const float*)d_in[6];  // [256]
    const float* w    = (const float*)d_in[7];  // [256]

    float* out      = (float*)d_out;            // [2,512,256]
    float* attn_out = out + BB * NN * DM;       // [2,512,512]

    kA<<<BB * NN / 4, 1024>>>(x, pos, Wx, bx, Wp, bp);
    kScore<<<(BB * NN / 4) * 4, 512>>>(w, attn_out);
    kSO<<<BB * NN / 4, 1024>>>(mask, out, attn_out);
}